// round 12
// baseline (speedup 1.0000x reference)
#include <cuda_runtime.h>
#include <cstdint>

// CapacityRouter: logits = x@W, top-2 routing with capacity masking.
// Outputs (concatenated float32): top_k_indices [N,2], top_k_weights [N,2],
// capacity_mask [N,2], expert_counters [64], num_dropped [1].

#define N_TOKENS 262144
#define HID      1024
#define NEXP     64
#define CAP      10240          // int(N*K/E * 1.25)
#define NBLK     2048           // N_TOKENS / 128
#define TWO_N    (2*N_TOKENS)
#define FOUR_N   (4*N_TOKENS)
#define SIX_N    (6*N_TOKENS)

typedef unsigned long long ull;

__device__ int g_hist[NBLK * NEXP];   // per-chunk expert histogram
__device__ int g_base[NBLK * NEXP];   // exclusive per-expert base per chunk

// ---- packed fp32x2 helpers (Blackwell 2x fp32 path) ----
__device__ __forceinline__ ull dupf(float a) {
    ull r; asm("mov.b64 %0, {%1, %1};" : "=l"(r) : "f"(a)); return r;
}
__device__ __forceinline__ void ffma2(ull& d, ull a, ull b) {
    asm("fma.rn.f32x2 %0, %1, %2, %0;" : "+l"(d) : "l"(a), "l"(b));
}
__device__ __forceinline__ void lds2(ull& a, ull& b, unsigned addr) {
    asm volatile("ld.shared.v2.b64 {%0, %1}, [%2];" : "=l"(a), "=l"(b) : "r"(addr));
}

struct __align__(16) SM1 {
    union {
        struct { float xs[32 * 129]; float ws[32 * 64]; } g;  // GEMM tiles
        float ls[128 * 66];                                    // logits exchange
    } u;
    int shist[64];
};

// ===================== Kernel 1: GEMM + top-2 + histogram =====================
// Block: 128 tokens x 64 experts. Warp w -> experts [8w, 8w+8), all 128 tokens
// (lane handles tokens lane, lane+32, lane+64, lane+96). K tiled by 32 with
// register prefetch double-buffering.
__global__ void __launch_bounds__(256)
k1_gemm_top2(const float* __restrict__ x, const float* __restrict__ W,
             float* __restrict__ out)
{
    __shared__ SM1 sm;
    const int tid  = threadIdx.x;
    const int lane = tid & 31;
    const int we   = (tid >> 5) * 8;                 // warp's first expert
    const long long T0 = (long long)blockIdx.x * 128;

    if (tid < 64) sm.shist[tid] = 0;

    ull acc[16];                                     // [token j][expert pair p]
    #pragma unroll
    for (int i = 0; i < 16; i++) acc[i] = 0ULL;

    const unsigned ws_addr = (unsigned)__cvta_generic_to_shared(sm.u.g.ws);

    const int kg = (tid & 7) * 4;    // x: k-subgroup within 32-k tile
    const int tb = tid >> 3;         // x: base token (0..31)
    const int cg = (tid & 15) * 4;   // W: expert subgroup
    const int rb = tid >> 4;         // W: base k-row (0..15)

    float4 rx[4]; float4 rw[2];
    // prefetch step 0
    #pragma unroll
    for (int i = 0; i < 4; i++)
        rx[i] = *(const float4*)(x + (T0 + tb + 32 * i) * HID + kg);
    #pragma unroll
    for (int i = 0; i < 2; i++)
        rw[i] = *(const float4*)(W + (long long)(rb + 16 * i) * NEXP + cg);

    for (int s = 0; s < 32; ++s) {
        __syncthreads();
        // stage tiles into smem.
        // xs layout [k][token], row stride 129 -> conflict-free loads & stores.
        #pragma unroll
        for (int i = 0; i < 4; i++) {
            int tk = tb + 32 * i;
            sm.u.g.xs[(kg + 0) * 129 + tk] = rx[i].x;
            sm.u.g.xs[(kg + 1) * 129 + tk] = rx[i].y;
            sm.u.g.xs[(kg + 2) * 129 + tk] = rx[i].z;
            sm.u.g.xs[(kg + 3) * 129 + tk] = rx[i].w;
        }
        #pragma unroll
        for (int i = 0; i < 2; i++)
            *(float4*)&sm.u.g.ws[(rb + 16 * i) * 64 + cg] = rw[i];
        __syncthreads();

        // prefetch next step (overlaps with compute below)
        if (s < 31) {
            const long long ko = (long long)(s + 1) * 32;
            #pragma unroll
            for (int i = 0; i < 4; i++)
                rx[i] = *(const float4*)(x + (T0 + tb + 32 * i) * HID + ko + kg);
            #pragma unroll
            for (int i = 0; i < 2; i++)
                rw[i] = *(const float4*)(W + (ko + rb + 16 * i) * NEXP + cg);
        }

        // compute: per k, 4 scalar x LDS (conflict-free), 2 broadcast LDS.128
        // for W (pre-paired), 16 FFMA2.
        #pragma unroll 8
        for (int k = 0; k < 32; k++) {
            const float* xr = sm.u.g.xs + k * 129 + lane;
            ull w01, w23, w45, w67;
            unsigned wa = ws_addr + (unsigned)((k * 64 + we) * 4);
            lds2(w01, w23, wa);
            lds2(w45, w67, wa + 16);
            ull x0 = dupf(xr[0]),  x1 = dupf(xr[32]);
            ull x2 = dupf(xr[64]), x3 = dupf(xr[96]);
            ffma2(acc[0],  x0, w01); ffma2(acc[1],  x0, w23);
            ffma2(acc[2],  x0, w45); ffma2(acc[3],  x0, w67);
            ffma2(acc[4],  x1, w01); ffma2(acc[5],  x1, w23);
            ffma2(acc[6],  x1, w45); ffma2(acc[7],  x1, w67);
            ffma2(acc[8],  x2, w01); ffma2(acc[9],  x2, w23);
            ffma2(acc[10], x2, w45); ffma2(acc[11], x2, w67);
            ffma2(acc[12], x3, w01); ffma2(acc[13], x3, w23);
            ffma2(acc[14], x3, w45); ffma2(acc[15], x3, w67);
        }
    }

    __syncthreads();
    // exchange logits through smem: ls[token][expert], row stride 66 (8B aligned)
    #pragma unroll
    for (int j = 0; j < 4; j++) {
        int tk = lane + 32 * j;
        #pragma unroll
        for (int p = 0; p < 4; p++)
            *(ull*)&sm.u.ls[tk * 66 + we + 2 * p] = acc[j * 4 + p];
    }
    __syncthreads();

    if (tid < 128) {
        const float* row = sm.u.ls + tid * 66;
        float v1 = -3.402823466e38f, v2 = -3.402823466e38f;
        int i1 = 0, i2 = 0;
        #pragma unroll
        for (int e = 0; e < NEXP; e++) {
            float v = row[e];
            if (v > v1)      { v2 = v1; i2 = i1; v1 = v; i1 = e; }
            else if (v > v2) { v2 = v;  i2 = e; }
        }
        // softmax is monotonic; top-k ratio needs only the top-2 logits:
        // w1 = 1/(1+exp(l2-l1)), w2 = exp(l2-l1)*w1
        float e2 = expf(v2 - v1);
        float r  = 1.0f / (1.0f + e2);
        long long gt = T0 + tid;
        out[2 * gt]             = (float)i1;
        out[2 * gt + 1]         = (float)i2;
        out[TWO_N + 2 * gt]     = r;
        out[TWO_N + 2 * gt + 1] = e2 * r;
        atomicAdd(&sm.shist[i1], 1);
        atomicAdd(&sm.shist[i2], 1);
    }
    __syncthreads();
    if (tid < 64) g_hist[blockIdx.x * 64 + tid] = sm.shist[tid];
}

// ===================== Kernel 2: per-expert exclusive scan over chunks ========
__global__ void __launch_bounds__(1024)
k2_scan(float* __restrict__ out)
{
    __shared__ int part[16 * 64];
    __shared__ int kept[64];
    const int tid = threadIdx.x;
    const int e = tid & 63;
    const int g = tid >> 6;           // 16 row-groups of 128 chunk-rows
    const int r0 = g * 128;

    int s = 0;
    for (int r = 0; r < 128; r++) s += g_hist[(r0 + r) * 64 + e];
    part[g * 64 + e] = s;
    __syncthreads();

    if (tid < 64) {
        int acc = 0;
        for (int gg = 0; gg < 16; gg++) {
            int t = part[gg * 64 + tid];
            part[gg * 64 + tid] = acc;   // exclusive group base
            acc += t;
        }
        int k = acc < CAP ? acc : CAP;
        out[SIX_N + tid] = (float)k;     // expert_counters
        kept[tid] = k;
    }
    __syncthreads();
    if (tid == 0) {
        int tot = 0;
        for (int i = 0; i < 64; i++) tot += kept[i];
        out[SIX_N + 64] = (float)(2 * N_TOKENS - tot);  // num_dropped
    }

    int base = part[g * 64 + e];
    for (int r = 0; r < 128; r++) {
        g_base[(r0 + r) * 64 + e] = base;
        base += g_hist[(r0 + r) * 64 + e];
    }
}

// ===================== Kernel 3: ordered capacity mask + weight finalize ======
__global__ void __launch_bounds__(256)
k3_mask(float* __restrict__ out)
{
    __shared__ int se[256];
    __shared__ int sbase[64];
    __shared__ unsigned char smk[256];
    const int b = blockIdx.x;
    const int tid = threadIdx.x;

    // assignment a = b*256 + tid; read expert index (exact in float)
    int e = (int)out[(long long)b * 256 + tid];
    se[tid] = e;
    if (tid < 64) sbase[tid] = g_base[b * 64 + tid];
    __syncthreads();

    // thread-per-expert ordered rank within the chunk (exact reference order)
    if (tid < 64) {
        int cnt = sbase[tid];
        #pragma unroll 4
        for (int i = 0; i < 256; i++) {
            if (se[i] == tid) { smk[i] = (cnt < CAP) ? 1 : 0; cnt++; }
        }
    }
    __syncthreads();

    if (tid < 128) {
        long long a = (long long)b * 256 + 2 * tid;
        float m0 = (float)smk[2 * tid];
        float m1 = (float)smk[2 * tid + 1];
        float w0 = out[TWO_N + a];
        float w1 = out[TWO_N + a + 1];
        float d = m0 + m1 + 1e-10f;
        out[TWO_N + a]      = w0 * m0 / d;
        out[TWO_N + a + 1]  = w1 * m1 / d;
        out[FOUR_N + a]     = m0;
        out[FOUR_N + a + 1] = m1;
    }
}

extern "C" void kernel_launch(void* const* d_in, const int* in_sizes, int n_in,
                              void* d_out, int out_size)
{
    const float* x = (const float*)d_in[0];
    const float* W = (const float*)d_in[1];
    if (n_in >= 2 && in_sizes[0] < in_sizes[1]) {  // safety: order by size
        const float* t = x; x = W; W = t;
    }
    float* out = (float*)d_out;

    k1_gemm_top2<<<NBLK, 256>>>(x, W, out);
    k2_scan<<<1, 1024>>>(out);
    k3_mask<<<NBLK, 256>>>(out);
}